// round 6
// baseline (speedup 1.0000x reference)
#include <cuda_runtime.h>

// CausalRevIN: B=16, T=8192, C=128, fp32.
// Warp-per-tile single-pass scan: tile = 32 timesteps x 128 channels,
// lane = 4 channels (float4). 4096 tiles, 1024 CTAs of 4 independent warps.
// No __syncthreads, no SMEM. Windowed warp-parallel decoupled lookback x2.

#define BB 16
#define TT 8192
#define SPW 32                  // timesteps per warp-tile
#define TPS 256                 // tiles per series
#define NTILE (BB * TPS)        // 4096

#define STD_MIN 1e-5f
#define MAX_VAL 100.0f

__device__ float4 g_aggA_nm[NTILE * 32];
__device__ float4 g_aggA_x [NTILE * 32];
__device__ float4 g_incA_nm[NTILE * 32];
__device__ float4 g_incA_x [NTILE * 32];
__device__ float4 g_aggC   [NTILE * 32];
__device__ float4 g_incC   [NTILE * 32];
__device__ int    g_stateA [NTILE];
__device__ int    g_stateC [NTILE];

__global__ void k_init() {
    int i = blockIdx.x * blockDim.x + threadIdx.x;
    if (i < NTILE) { g_stateA[i] = 0; g_stateC[i] = 0; }
}

__device__ __forceinline__ void f4add(float4& a, const float4 b) {
    a.x += b.x; a.y += b.y; a.z += b.z; a.w += b.w;
}

__global__ void __launch_bounds__(128, 7) k_main(const float* __restrict__ x,
                                                 const float* __restrict__ m,
                                                 float* __restrict__ out) {
    const int tid  = threadIdx.x;
    const int w    = tid >> 5;
    const int l    = tid & 31;
    const int tile = blockIdx.x * 4 + w;
    const int b    = tile >> 8;
    const int seg  = tile & (TPS - 1);
    const int bbase = b << 8;

    const float4* __restrict__ x4 = (const float4*)x;
    const float4* __restrict__ m4 = (const float4*)m;
    float4* __restrict__ o4 = (float4*)out;
    const int rowbase = (b * TT + seg * SPW) * 32 + l;   // float4 index, max 4.19M

    // ================= Phase 1: load, pack mask bits, sum x =================
    float4 sx = make_float4(0.f, 0.f, 0.f, 0.f);
    unsigned nb0 = 0, nb1 = 0, nb2 = 0, nb3 = 0;
    #pragma unroll 8
    for (int t = 0; t < SPW; t++) {
        float4 xv = x4[rowbase + t * 32];
        float4 mv = __ldcs(&m4[rowbase + t * 32]);
        f4add(sx, xv);
        if (mv.x == 0.f) nb0 |= 1u << t;
        if (mv.y == 0.f) nb1 |= 1u << t;
        if (mv.z == 0.f) nb2 |= 1u << t;
        if (mv.w == 0.f) nb3 |= 1u << t;
    }
    float4 snm = make_float4((float)__popc(nb0), (float)__popc(nb1),
                             (float)__popc(nb2), (float)__popc(nb3));

    // ================= Lookback A =================
    float4 ex_nm = make_float4(0.f, 0.f, 0.f, 0.f);
    float4 ex_x  = make_float4(0.f, 0.f, 0.f, 0.f);
    if (seg != 0) {
        g_aggA_nm[tile * 32 + l] = snm;
        g_aggA_x [tile * 32 + l] = sx;
        __threadfence();
        __syncwarp();
        if (l == 0) atomicExch(&g_stateA[tile], 1);

        int p_end = seg;
        for (;;) {
            int cnt = p_end < 32 ? p_end : 32;
            int s = 2;
            if (l < cnt) {
                int pp = bbase + p_end - 1 - l;
                do { s = atomicAdd(&g_stateA[pp], 0); } while (s == 0);
            }
            unsigned incmask = __ballot_sync(0xffffffffu, (s == 2) && (l < cnt));
            __threadfence();
            int li = incmask ? (__ffs(incmask) - 1) : -1;
            int nagg = (li >= 0) ? li : cnt;
            for (int j = 0; j < nagg; j++) {
                int pidx = (bbase + p_end - 1 - j) * 32 + l;
                f4add(ex_nm, __ldcg(&g_aggA_nm[pidx]));
                f4add(ex_x,  __ldcg(&g_aggA_x [pidx]));
            }
            if (li >= 0) {
                int pidx = (bbase + p_end - 1 - li) * 32 + l;
                f4add(ex_nm, __ldcg(&g_incA_nm[pidx]));
                f4add(ex_x,  __ldcg(&g_incA_x [pidx]));
                break;
            }
            p_end -= cnt;
        }
    }
    {
        float4 in_nm = ex_nm, in_x = ex_x;
        f4add(in_nm, snm); f4add(in_x, sx);
        g_incA_nm[tile * 32 + l] = in_nm;
        g_incA_x [tile * 32 + l] = in_x;
        __threadfence();
        __syncwarp();
        if (l == 0) atomicExch(&g_stateA[tile], 2);
    }

    // ================= Phase 2: local sum of ((x-mean)*nm)^2 =================
    float4 cn = ex_nm, cx = ex_x;
    float4 lss = make_float4(0.f, 0.f, 0.f, 0.f);
    #pragma unroll 8
    for (int t = 0; t < SPW; t++) {
        float4 xv = x4[rowbase + t * 32];
        #define STEP2(k, bits)                                            \
        {                                                                 \
            float nm = (bits & (1u << t)) ? 1.f : 0.f;                    \
            cn.k += nm; cx.k += xv.k;                                     \
            float n = fmaxf(cn.k, 1.f);                                   \
            float mean = cx.k * __fdividef(1.f, n);                       \
            float d = (xv.k - mean) * nm;                                 \
            lss.k += d * d;                                               \
        }
        STEP2(x, nb0) STEP2(y, nb1) STEP2(z, nb2) STEP2(w, nb3)
        #undef STEP2
    }

    // ================= Lookback C =================
    float4 ex_s = make_float4(0.f, 0.f, 0.f, 0.f);
    if (seg != 0) {
        g_aggC[tile * 32 + l] = lss;
        __threadfence();
        __syncwarp();
        if (l == 0) atomicExch(&g_stateC[tile], 1);

        int p_end = seg;
        for (;;) {
            int cnt = p_end < 32 ? p_end : 32;
            int s = 2;
            if (l < cnt) {
                int pp = bbase + p_end - 1 - l;
                do { s = atomicAdd(&g_stateC[pp], 0); } while (s == 0);
            }
            unsigned incmask = __ballot_sync(0xffffffffu, (s == 2) && (l < cnt));
            __threadfence();
            int li = incmask ? (__ffs(incmask) - 1) : -1;
            int nagg = (li >= 0) ? li : cnt;
            for (int j = 0; j < nagg; j++)
                f4add(ex_s, __ldcg(&g_aggC[(bbase + p_end - 1 - j) * 32 + l]));
            if (li >= 0) {
                f4add(ex_s, __ldcg(&g_incC[(bbase + p_end - 1 - li) * 32 + l]));
                break;
            }
            p_end -= cnt;
        }
    }
    {
        float4 in_s = ex_s; f4add(in_s, lss);
        g_incC[tile * 32 + l] = in_s;
        __threadfence();
        __syncwarp();
        if (l == 0) atomicExch(&g_stateC[tile], 2);
    }

    // ================= Phase 3: normalize + clip, write out =================
    cn = ex_nm; cx = ex_x;
    float4 cs = ex_s;
    #pragma unroll 8
    for (int t = 0; t < SPW; t++) {
        float4 xv = __ldcs(&x4[rowbase + t * 32]);
        float4 ov;
        #define STEP3(k, bits)                                            \
        {                                                                 \
            float nm = (bits & (1u << t)) ? 1.f : 0.f;                    \
            cn.k += nm; cx.k += xv.k;                                     \
            float n = fmaxf(cn.k, 1.f);                                   \
            float rn = __fdividef(1.f, n);                                \
            float mean = cx.k * rn;                                       \
            float num = xv.k - mean;                                      \
            float d = num * nm;                                           \
            cs.k += d * d;                                                \
            float var = cs.k * rn;                                        \
            float res = (var > STD_MIN * STD_MIN) ? num * rsqrtf(var) : num; \
            ov.k = fminf(fmaxf(res, -MAX_VAL), MAX_VAL);                  \
        }
        STEP3(x, nb0) STEP3(y, nb1) STEP3(z, nb2) STEP3(w, nb3)
        #undef STEP3
        __stcs(&o4[rowbase + t * 32], ov);
    }
}

extern "C" void kernel_launch(void* const* d_in, const int* in_sizes, int n_in,
                              void* d_out, int out_size) {
    const float* x = (const float*)d_in[0];
    const float* m = (const float*)d_in[1];
    float* out = (float*)d_out;

    k_init<<<(NTILE + 255) / 256, 256>>>();
    k_main<<<NTILE / 4, 128>>>(x, m, out);
}

// round 7
// speedup vs baseline: 1.0221x; 1.0221x over previous
#include <cuda_runtime.h>

// CausalRevIN: B=16, T=8192, C=128, fp32.
// Single-pass scan. Tile = 128 timesteps (4 warps x 32 t), thread = 4 channels (float4).
// 1024 CTAs, 7 CTAs/SM resident. Relaxed-load flag polls (no atomic spin).

#define BB 16
#define TT 8192
#define TILE_T 128
#define SPW 32
#define SPB 64                  // tiles per series
#define NTILE (BB * SPB)        // 1024

#define STD_MIN 1e-5f
#define MAX_VAL 100.0f

__device__ float4 g_aggA_nm[NTILE * 32];
__device__ float4 g_aggA_x [NTILE * 32];
__device__ float4 g_incA_nm[NTILE * 32];
__device__ float4 g_incA_x [NTILE * 32];
__device__ float4 g_aggC   [NTILE * 32];
__device__ float4 g_incC   [NTILE * 32];
__device__ int    g_stateA [NTILE];
__device__ int    g_stateC [NTILE];
__device__ int    g_ticket;

__global__ void k_init() {
    int i = blockIdx.x * blockDim.x + threadIdx.x;
    if (i < NTILE) { g_stateA[i] = 0; g_stateC[i] = 0; }
    if (i == 0) g_ticket = 0;
}

__device__ __forceinline__ void f4add(float4& a, const float4 b) {
    a.x += b.x; a.y += b.y; a.z += b.z; a.w += b.w;
}

__device__ __forceinline__ int ld_flag_relaxed(const int* p) {
    int v;
    asm volatile("ld.relaxed.gpu.global.b32 %0, [%1];" : "=r"(v) : "l"(p));
    return v;
}

__device__ __forceinline__ void st_flag_release(int* p, int v) {
    asm volatile("st.release.gpu.global.b32 [%0], %1;" :: "l"(p), "r"(v) : "memory");
}

__global__ void __launch_bounds__(128, 7) k_main(const float* __restrict__ x,
                                                 const float* __restrict__ m,
                                                 float* __restrict__ out) {
    __shared__ float4 s_a[128];
    __shared__ float4 s_b[128];
    __shared__ int sh_tile;

    const int tid = threadIdx.x;
    if (tid == 0) sh_tile = atomicAdd(&g_ticket, 1);
    __syncthreads();
    const int tile = sh_tile;
    const int b   = tile >> 6;
    const int seg = tile & (SPB - 1);
    const int w   = tid >> 5;
    const int l   = tid & 31;
    const int bbase = b << 6;

    const float4* __restrict__ x4 = (const float4*)x;
    const float4* __restrict__ m4 = (const float4*)m;
    float4* __restrict__ o4 = (float4*)out;
    const int rowbase = (b * TT + seg * TILE_T + w * SPW) * 32 + l;

    // ================= Phase 1: load, pack mask bits, sum x =================
    float4 sx = make_float4(0.f, 0.f, 0.f, 0.f);
    unsigned nb0 = 0, nb1 = 0, nb2 = 0, nb3 = 0;
    #pragma unroll 8
    for (int t = 0; t < SPW; t++) {
        float4 xv = x4[rowbase + t * 32];
        float4 mv = __ldcs(&m4[rowbase + t * 32]);
        f4add(sx, xv);
        if (mv.x == 0.f) nb0 |= 1u << t;
        if (mv.y == 0.f) nb1 |= 1u << t;
        if (mv.z == 0.f) nb2 |= 1u << t;
        if (mv.w == 0.f) nb3 |= 1u << t;
    }
    float4 snm = make_float4((float)__popc(nb0), (float)__popc(nb1),
                             (float)__popc(nb2), (float)__popc(nb3));
    s_a[tid] = snm; s_b[tid] = sx;
    __syncthreads();

    // exclusive prefix over warps (same lane) + CTA totals for warp 0
    float4 we_nm = make_float4(0.f, 0.f, 0.f, 0.f);
    float4 we_x  = make_float4(0.f, 0.f, 0.f, 0.f);
    #pragma unroll
    for (int ww = 0; ww < 3; ww++) {
        if (ww < w) { f4add(we_nm, s_a[ww * 32 + l]); f4add(we_x, s_b[ww * 32 + l]); }
    }
    float4 tot_nm, tot_x;
    if (w == 0) {
        tot_nm = s_a[l];            tot_x = s_b[l];
        f4add(tot_nm, s_a[32 + l]); f4add(tot_x, s_b[32 + l]);
        f4add(tot_nm, s_a[64 + l]); f4add(tot_x, s_b[64 + l]);
        f4add(tot_nm, s_a[96 + l]); f4add(tot_x, s_b[96 + l]);
    }
    __syncthreads();

    // ================= Lookback A (warp 0) =================
    if (w == 0) {
        float4 ex_nm = make_float4(0.f, 0.f, 0.f, 0.f);
        float4 ex_x  = make_float4(0.f, 0.f, 0.f, 0.f);
        if (seg != 0) {
            g_aggA_nm[tile * 32 + l] = tot_nm;
            g_aggA_x [tile * 32 + l] = tot_x;
            __threadfence();
            __syncwarp();
            if (l == 0) st_flag_release(&g_stateA[tile], 1);

            int p_end = seg;
            for (;;) {
                int cnt = p_end < 32 ? p_end : 32;
                int s = 2;
                if (l < cnt) {
                    const int* fp = &g_stateA[bbase + p_end - 1 - l];
                    s = ld_flag_relaxed(fp);
                    while (s == 0) { __nanosleep(20); s = ld_flag_relaxed(fp); }
                }
                unsigned incmask = __ballot_sync(0xffffffffu, (s == 2) && (l < cnt));
                __threadfence();            // acquire: order value reads after flags
                int li = incmask ? (__ffs(incmask) - 1) : -1;
                int nagg = (li >= 0) ? li : cnt;
                for (int j = 0; j < nagg; j++) {
                    int pidx = (bbase + p_end - 1 - j) * 32 + l;
                    f4add(ex_nm, __ldcg(&g_aggA_nm[pidx]));
                    f4add(ex_x,  __ldcg(&g_aggA_x [pidx]));
                }
                if (li >= 0) {
                    int pidx = (bbase + p_end - 1 - li) * 32 + l;
                    f4add(ex_nm, __ldcg(&g_incA_nm[pidx]));
                    f4add(ex_x,  __ldcg(&g_incA_x [pidx]));
                    break;
                }
                p_end -= cnt;
            }
        }
        float4 in_nm = ex_nm, in_x = ex_x;
        f4add(in_nm, tot_nm); f4add(in_x, tot_x);
        g_incA_nm[tile * 32 + l] = in_nm;
        g_incA_x [tile * 32 + l] = in_x;
        __threadfence();
        __syncwarp();
        if (l == 0) st_flag_release(&g_stateA[tile], 2);
        s_a[l] = ex_nm; s_b[l] = ex_x;
    }
    __syncthreads();
    float4 base_n = s_a[l], base_x = s_b[l];
    f4add(base_n, we_nm); f4add(base_x, we_x);

    // ================= Phase 2: local sum of ((x-mean)*nm)^2 =================
    float4 cn = base_n, cx = base_x;
    float4 lss = make_float4(0.f, 0.f, 0.f, 0.f);
    #pragma unroll 8
    for (int t = 0; t < SPW; t++) {
        float4 xv = x4[rowbase + t * 32];
        #define STEP2(k, bits)                                            \
        {                                                                 \
            float nm = (bits & (1u << t)) ? 1.f : 0.f;                    \
            cn.k += nm; cx.k += xv.k;                                     \
            float n = fmaxf(cn.k, 1.f);                                   \
            float mean = cx.k * __fdividef(1.f, n);                       \
            float d = (xv.k - mean) * nm;                                 \
            lss.k += d * d;                                               \
        }
        STEP2(x, nb0) STEP2(y, nb1) STEP2(z, nb2) STEP2(w, nb3)
        #undef STEP2
    }
    __syncthreads();
    s_a[tid] = lss;
    __syncthreads();
    float4 we_s = make_float4(0.f, 0.f, 0.f, 0.f);
    #pragma unroll
    for (int ww = 0; ww < 3; ww++) {
        if (ww < w) f4add(we_s, s_a[ww * 32 + l]);
    }
    float4 tot_s;
    if (w == 0) {
        tot_s = s_a[l];
        f4add(tot_s, s_a[32 + l]); f4add(tot_s, s_a[64 + l]); f4add(tot_s, s_a[96 + l]);
    }
    __syncthreads();

    // ================= Lookback C (warp 0) =================
    if (w == 0) {
        float4 ex_s = make_float4(0.f, 0.f, 0.f, 0.f);
        if (seg != 0) {
            g_aggC[tile * 32 + l] = tot_s;
            __threadfence();
            __syncwarp();
            if (l == 0) st_flag_release(&g_stateC[tile], 1);

            int p_end = seg;
            for (;;) {
                int cnt = p_end < 32 ? p_end : 32;
                int s = 2;
                if (l < cnt) {
                    const int* fp = &g_stateC[bbase + p_end - 1 - l];
                    s = ld_flag_relaxed(fp);
                    while (s == 0) { __nanosleep(20); s = ld_flag_relaxed(fp); }
                }
                unsigned incmask = __ballot_sync(0xffffffffu, (s == 2) && (l < cnt));
                __threadfence();
                int li = incmask ? (__ffs(incmask) - 1) : -1;
                int nagg = (li >= 0) ? li : cnt;
                for (int j = 0; j < nagg; j++)
                    f4add(ex_s, __ldcg(&g_aggC[(bbase + p_end - 1 - j) * 32 + l]));
                if (li >= 0) {
                    f4add(ex_s, __ldcg(&g_incC[(bbase + p_end - 1 - li) * 32 + l]));
                    break;
                }
                p_end -= cnt;
            }
        }
        float4 in_s = ex_s; f4add(in_s, tot_s);
        g_incC[tile * 32 + l] = in_s;
        __threadfence();
        __syncwarp();
        if (l == 0) st_flag_release(&g_stateC[tile], 2);
        s_a[l] = ex_s;
    }
    __syncthreads();
    float4 base_s = s_a[l];
    f4add(base_s, we_s);

    // ================= Phase 3: normalize + clip, write out =================
    cn = base_n; cx = base_x;
    float4 cs = base_s;
    #pragma unroll 8
    for (int t = 0; t < SPW; t++) {
        float4 xv = __ldcs(&x4[rowbase + t * 32]);
        float4 ov;
        #define STEP3(k, bits)                                            \
        {                                                                 \
            float nm = (bits & (1u << t)) ? 1.f : 0.f;                    \
            cn.k += nm; cx.k += xv.k;                                     \
            float n = fmaxf(cn.k, 1.f);                                   \
            float rn = __fdividef(1.f, n);                                \
            float mean = cx.k * rn;                                       \
            float num = xv.k - mean;                                      \
            float d = num * nm;                                           \
            cs.k += d * d;                                                \
            float var = cs.k * rn;                                        \
            float res = (var > STD_MIN * STD_MIN) ? num * rsqrtf(var) : num; \
            ov.k = fminf(fmaxf(res, -MAX_VAL), MAX_VAL);                  \
        }
        STEP3(x, nb0) STEP3(y, nb1) STEP3(z, nb2) STEP3(w, nb3)
        #undef STEP3
        __stcs(&o4[rowbase + t * 32], ov);
    }
}

extern "C" void kernel_launch(void* const* d_in, const int* in_sizes, int n_in,
                              void* d_out, int out_size) {
    const float* x = (const float*)d_in[0];
    const float* m = (const float*)d_in[1];
    float* out = (float*)d_out;

    k_init<<<(NTILE + 255) / 256, 256>>>();
    k_main<<<NTILE, 128>>>(x, m, out);
}

// round 8
// speedup vs baseline: 1.2187x; 1.1924x over previous
#include <cuda_runtime.h>

// CausalRevIN: B=16, T=8192, C=128, fp32.
// Single-pass scan. Tile = 128 timesteps (4 warps x 32 t), thread = 4 channels (float4).
// 1024 CTAs (single resident wave), windowed warp-parallel decoupled lookback x2.
// r5 structure (best measured) + popc/fmax micro-opts, no ticket.

#define BB 16
#define TT 8192
#define TILE_T 128
#define SPW 32
#define SPB 64                  // tiles per series
#define NTILE (BB * SPB)        // 1024

#define STD_MIN 1e-5f
#define MAX_VAL 100.0f

__device__ float4 g_aggA_nm[NTILE * 32];
__device__ float4 g_aggA_x [NTILE * 32];
__device__ float4 g_incA_nm[NTILE * 32];
__device__ float4 g_incA_x [NTILE * 32];
__device__ float4 g_aggC   [NTILE * 32];
__device__ float4 g_incC   [NTILE * 32];
__device__ int    g_stateA [NTILE];
__device__ int    g_stateC [NTILE];

__global__ void k_init() {
    int i = blockIdx.x * blockDim.x + threadIdx.x;
    if (i < NTILE) { g_stateA[i] = 0; g_stateC[i] = 0; }
}

__device__ __forceinline__ void f4add(float4& a, const float4 b) {
    a.x += b.x; a.y += b.y; a.z += b.z; a.w += b.w;
}

__global__ void __launch_bounds__(128, 7) k_main(const float* __restrict__ x,
                                                 const float* __restrict__ m,
                                                 float* __restrict__ out) {
    __shared__ float4 s_a[128];
    __shared__ float4 s_b[128];

    const int tid  = threadIdx.x;
    const int tile = blockIdx.x;
    const int b    = tile >> 6;
    const int seg  = tile & (SPB - 1);
    const int w    = tid >> 5;
    const int l    = tid & 31;
    const int bbase = b << 6;

    const float4* __restrict__ x4 = (const float4*)x;
    const float4* __restrict__ m4 = (const float4*)m;
    float4* __restrict__ o4 = (float4*)out;
    const int rowbase = (b * TT + seg * TILE_T + w * SPW) * 32 + l;

    // ================= Phase 1: load, pack mask bits, sum x =================
    float4 sx = make_float4(0.f, 0.f, 0.f, 0.f);
    unsigned nb0 = 0, nb1 = 0, nb2 = 0, nb3 = 0;
    #pragma unroll 8
    for (int t = 0; t < SPW; t++) {
        float4 xv = x4[rowbase + t * 32];
        float4 mv = __ldcs(&m4[rowbase + t * 32]);
        f4add(sx, xv);
        if (mv.x == 0.f) nb0 |= 1u << t;
        if (mv.y == 0.f) nb1 |= 1u << t;
        if (mv.z == 0.f) nb2 |= 1u << t;
        if (mv.w == 0.f) nb3 |= 1u << t;
    }
    float4 snm = make_float4((float)__popc(nb0), (float)__popc(nb1),
                             (float)__popc(nb2), (float)__popc(nb3));
    s_a[tid] = snm; s_b[tid] = sx;
    __syncthreads();

    // exclusive prefix over warps (same lane) + CTA totals for warp 0
    float4 we_nm = make_float4(0.f, 0.f, 0.f, 0.f);
    float4 we_x  = make_float4(0.f, 0.f, 0.f, 0.f);
    for (int ww = 0; ww < w; ww++) { f4add(we_nm, s_a[ww * 32 + l]); f4add(we_x, s_b[ww * 32 + l]); }
    float4 tot_nm, tot_x;
    if (w == 0) {
        tot_nm = s_a[l];            tot_x = s_b[l];
        f4add(tot_nm, s_a[32 + l]); f4add(tot_x, s_b[32 + l]);
        f4add(tot_nm, s_a[64 + l]); f4add(tot_x, s_b[64 + l]);
        f4add(tot_nm, s_a[96 + l]); f4add(tot_x, s_b[96 + l]);
    }
    __syncthreads();

    // ================= Lookback A (warp 0) =================
    if (w == 0) {
        float4 ex_nm = make_float4(0.f, 0.f, 0.f, 0.f);
        float4 ex_x  = make_float4(0.f, 0.f, 0.f, 0.f);
        if (seg != 0) {
            g_aggA_nm[tile * 32 + l] = tot_nm;
            g_aggA_x [tile * 32 + l] = tot_x;
            __threadfence();
            __syncwarp();
            if (l == 0) atomicExch(&g_stateA[tile], 1);

            int p_end = seg;
            for (;;) {
                int cnt = p_end < 32 ? p_end : 32;
                int s = 2;
                if (l < cnt) {
                    int pp = bbase + p_end - 1 - l;
                    do { s = atomicAdd(&g_stateA[pp], 0); } while (s == 0);
                }
                unsigned incmask = __ballot_sync(0xffffffffu, (s == 2) && (l < cnt));
                __threadfence();
                int li = incmask ? (__ffs(incmask) - 1) : -1;
                int nagg = (li >= 0) ? li : cnt;
                for (int j = 0; j < nagg; j++) {
                    int pidx = (bbase + p_end - 1 - j) * 32 + l;
                    f4add(ex_nm, __ldcg(&g_aggA_nm[pidx]));
                    f4add(ex_x,  __ldcg(&g_aggA_x [pidx]));
                }
                if (li >= 0) {
                    int pidx = (bbase + p_end - 1 - li) * 32 + l;
                    f4add(ex_nm, __ldcg(&g_incA_nm[pidx]));
                    f4add(ex_x,  __ldcg(&g_incA_x [pidx]));
                    break;
                }
                p_end -= cnt;
            }
        }
        float4 in_nm = ex_nm, in_x = ex_x;
        f4add(in_nm, tot_nm); f4add(in_x, tot_x);
        g_incA_nm[tile * 32 + l] = in_nm;
        g_incA_x [tile * 32 + l] = in_x;
        __threadfence();
        __syncwarp();
        if (l == 0) atomicExch(&g_stateA[tile], 2);
        s_a[l] = ex_nm; s_b[l] = ex_x;
    }
    __syncthreads();
    float4 base_n = s_a[l], base_x = s_b[l];
    f4add(base_n, we_nm); f4add(base_x, we_x);

    // ================= Phase 2: local sum of ((x-mean)*nm)^2 =================
    float4 cn = base_n, cx = base_x;
    float4 lss = make_float4(0.f, 0.f, 0.f, 0.f);
    #pragma unroll 8
    for (int t = 0; t < SPW; t++) {
        float4 xv = x4[rowbase + t * 32];
        #define STEP2(k, bits)                                            \
        {                                                                 \
            float nm = (bits & (1u << t)) ? 1.f : 0.f;                    \
            cn.k += nm; cx.k += xv.k;                                     \
            float n = fmaxf(cn.k, 1.f);                                   \
            float mean = cx.k * __fdividef(1.f, n);                       \
            float d = (xv.k - mean) * nm;                                 \
            lss.k += d * d;                                               \
        }
        STEP2(x, nb0) STEP2(y, nb1) STEP2(z, nb2) STEP2(w, nb3)
        #undef STEP2
    }
    __syncthreads();
    s_a[tid] = lss;
    __syncthreads();
    float4 we_s = make_float4(0.f, 0.f, 0.f, 0.f);
    for (int ww = 0; ww < w; ww++) f4add(we_s, s_a[ww * 32 + l]);
    float4 tot_s;
    if (w == 0) {
        tot_s = s_a[l];
        f4add(tot_s, s_a[32 + l]); f4add(tot_s, s_a[64 + l]); f4add(tot_s, s_a[96 + l]);
    }
    __syncthreads();

    // ================= Lookback C (warp 0) =================
    if (w == 0) {
        float4 ex_s = make_float4(0.f, 0.f, 0.f, 0.f);
        if (seg != 0) {
            g_aggC[tile * 32 + l] = tot_s;
            __threadfence();
            __syncwarp();
            if (l == 0) atomicExch(&g_stateC[tile], 1);

            int p_end = seg;
            for (;;) {
                int cnt = p_end < 32 ? p_end : 32;
                int s = 2;
                if (l < cnt) {
                    int pp = bbase + p_end - 1 - l;
                    do { s = atomicAdd(&g_stateC[pp], 0); } while (s == 0);
                }
                unsigned incmask = __ballot_sync(0xffffffffu, (s == 2) && (l < cnt));
                __threadfence();
                int li = incmask ? (__ffs(incmask) - 1) : -1;
                int nagg = (li >= 0) ? li : cnt;
                for (int j = 0; j < nagg; j++)
                    f4add(ex_s, __ldcg(&g_aggC[(bbase + p_end - 1 - j) * 32 + l]));
                if (li >= 0) {
                    f4add(ex_s, __ldcg(&g_incC[(bbase + p_end - 1 - li) * 32 + l]));
                    break;
                }
                p_end -= cnt;
            }
        }
        float4 in_s = ex_s; f4add(in_s, tot_s);
        g_incC[tile * 32 + l] = in_s;
        __threadfence();
        __syncwarp();
        if (l == 0) atomicExch(&g_stateC[tile], 2);
        s_a[l] = ex_s;
    }
    __syncthreads();
    float4 base_s = s_a[l];
    f4add(base_s, we_s);

    // ================= Phase 3: normalize + clip, write out =================
    cn = base_n; cx = base_x;
    float4 cs = base_s;
    #pragma unroll 8
    for (int t = 0; t < SPW; t++) {
        float4 xv = __ldcs(&x4[rowbase + t * 32]);
        float4 ov;
        #define STEP3(k, bits)                                            \
        {                                                                 \
            float nm = (bits & (1u << t)) ? 1.f : 0.f;                    \
            cn.k += nm; cx.k += xv.k;                                     \
            float n = fmaxf(cn.k, 1.f);                                   \
            float rn = __fdividef(1.f, n);                                \
            float mean = cx.k * rn;                                       \
            float num = xv.k - mean;                                      \
            float d = num * nm;                                           \
            cs.k += d * d;                                                \
            float var = cs.k * rn;                                        \
            float res = (var > STD_MIN * STD_MIN) ? num * rsqrtf(var) : num; \
            ov.k = fminf(fmaxf(res, -MAX_VAL), MAX_VAL);                  \
        }
        STEP3(x, nb0) STEP3(y, nb1) STEP3(z, nb2) STEP3(w, nb3)
        #undef STEP3
        __stcs(&o4[rowbase + t * 32], ov);
    }
}

extern "C" void kernel_launch(void* const* d_in, const int* in_sizes, int n_in,
                              void* d_out, int out_size) {
    const float* x = (const float*)d_in[0];
    const float* m = (const float*)d_in[1];
    float* out = (float*)d_out;

    k_init<<<(NTILE + 255) / 256, 256>>>();
    k_main<<<NTILE, 128>>>(x, m, out);
}